// round 1
// baseline (speedup 1.0000x reference)
#include <cuda_runtime.h>
#include <math.h>

#define NB    32     // batch
#define LSEQ  1024
#define CH    34
#define D     256
#define NE    8
#define NP    4      // only first 4 patches survive the [:, :seq_len] slice
#define PL    16
#define PRED  96

// Scratch (device globals — no allocation allowed)
__device__ float g_xp[NB][NP][D];
__device__ float g_gates[NB][NP][NE];
__device__ float g_stats[NB][2];              // mean, stdev
__device__ float g_partial[NB][NE][NP * D];   // gated expert partials

// ---------------------------------------------------------------------------
// K1: per-b stats, patch projection, router softmax
// grid = 32 blocks, 256 threads
// ---------------------------------------------------------------------------
__global__ void k1_prep(const float* __restrict__ x,
                        const float* __restrict__ W_proj,
                        const float* __restrict__ b_proj,
                        const float* __restrict__ W_router,
                        const float* __restrict__ b_router) {
    const int b   = blockIdx.x;
    const int tid = threadIdx.x;

    __shared__ float red1[256];
    __shared__ float red2[256];
    __shared__ float xn[NP * PL];        // 64 normalized inputs
    __shared__ float s_xp[NP][D];
    __shared__ float s_logit[NP][NE];
    __shared__ float s_mean, s_inv;

    // Load channel 2 of x[b, :, :]; 4 elems per thread
    const float* xb = x + (size_t)b * LSEQ * CH + 2;
    float v0 = xb[(tid        ) * CH];
    float v1 = xb[(tid +  256 ) * CH];
    float v2 = xb[(tid +  512 ) * CH];
    float v3 = xb[(tid +  768 ) * CH];
    float sum = v0 + v1 + v2 + v3;
    float sq  = v0*v0 + v1*v1 + v2*v2 + v3*v3;

    red1[tid] = sum; red2[tid] = sq;
    __syncthreads();
    #pragma unroll
    for (int s = 128; s > 0; s >>= 1) {
        if (tid < s) { red1[tid] += red1[tid + s]; red2[tid] += red2[tid + s]; }
        __syncthreads();
    }
    if (tid == 0) {
        float mean = red1[0] * (1.0f / LSEQ);
        float var  = red2[0] * (1.0f / LSEQ) - mean * mean;
        float std  = sqrtf(var + 1e-5f);
        s_mean = mean;
        s_inv  = 1.0f / std;
        g_stats[b][0] = mean;
        g_stats[b][1] = std;
    }
    __syncthreads();

    // Normalized first 64 values (l = tid corresponds to v0)
    if (tid < NP * PL) xn[tid] = (v0 - s_mean) * s_inv;
    __syncthreads();

    // xp[p][d] = b_proj[d] + sum_k W_proj[d][k] * xn[p*16+k]
    {
        const int d = tid;
        const float* wr = W_proj + d * PL;
        float w[PL];
        #pragma unroll
        for (int k = 0; k < PL; k++) w[k] = wr[k];
        #pragma unroll
        for (int p = 0; p < NP; p++) {
            float acc = b_proj[d];
            #pragma unroll
            for (int k = 0; k < PL; k++) acc = fmaf(w[k], xn[p * PL + k], acc);
            s_xp[p][d] = acc;
            g_xp[b][p][d] = acc;
        }
    }
    __syncthreads();

    // Router logits: 32 (p,e) pairs on first warp
    if (tid < NP * NE) {
        const int p = tid >> 3, e = tid & 7;
        const float* wr = W_router + e * D;
        float acc = b_router[e];
        #pragma unroll 8
        for (int d = 0; d < D; d++) acc = fmaf(wr[d], s_xp[p][d], acc);
        s_logit[p][e] = acc;
    }
    __syncthreads();
    if (tid < NP * NE) {
        const int p = tid >> 3, e = tid & 7;
        float m = s_logit[p][0];
        #pragma unroll
        for (int j = 1; j < NE; j++) m = fmaxf(m, s_logit[p][j]);
        float denom = 0.f;
        #pragma unroll
        for (int j = 0; j < NE; j++) denom += __expf(s_logit[p][j] - m);
        g_gates[b][p][e] = __expf(s_logit[p][e] - m) / denom;
    }
}

// ---------------------------------------------------------------------------
// K2: per-(b,e) gated expert partials.  grid = 256 blocks, 256 threads
// thread h: acc[p] = xp[p] . W_experts[e][h][:]  (4 patches reuse each load)
// ---------------------------------------------------------------------------
__global__ void k2_experts(const float* __restrict__ W_experts,
                           const float* __restrict__ b_experts) {
    const int bx = blockIdx.x;
    const int b  = bx >> 3;
    const int e  = bx & 7;
    const int tid = threadIdx.x;

    __shared__ float4 s_xp4[NP * D / 4];   // 256 float4
    __shared__ float  s_g[NP];

    s_xp4[tid] = reinterpret_cast<const float4*>(&g_xp[b][0][0])[tid];
    if (tid < NP) s_g[tid] = g_gates[b][tid][e];
    __syncthreads();

    const int h = tid;
    const float4* w = reinterpret_cast<const float4*>(
        W_experts + ((size_t)(e * D + h)) * D);

    float a0 = 0.f, a1 = 0.f, a2 = 0.f, a3 = 0.f;
    #pragma unroll 8
    for (int i = 0; i < D / 4; i++) {
        float4 wv = w[i];
        float4 x0 = s_xp4[0 * 64 + i];
        float4 x1 = s_xp4[1 * 64 + i];
        float4 x2 = s_xp4[2 * 64 + i];
        float4 x3 = s_xp4[3 * 64 + i];
        a0 = fmaf(wv.x, x0.x, a0); a0 = fmaf(wv.y, x0.y, a0);
        a0 = fmaf(wv.z, x0.z, a0); a0 = fmaf(wv.w, x0.w, a0);
        a1 = fmaf(wv.x, x1.x, a1); a1 = fmaf(wv.y, x1.y, a1);
        a1 = fmaf(wv.z, x1.z, a1); a1 = fmaf(wv.w, x1.w, a1);
        a2 = fmaf(wv.x, x2.x, a2); a2 = fmaf(wv.y, x2.y, a2);
        a2 = fmaf(wv.z, x2.z, a2); a2 = fmaf(wv.w, x2.w, a2);
        a3 = fmaf(wv.x, x3.x, a3); a3 = fmaf(wv.y, x3.y, a3);
        a3 = fmaf(wv.z, x3.z, a3); a3 = fmaf(wv.w, x3.w, a3);
    }
    const float be = b_experts[e * D + h];
    g_partial[b][e][0 * D + h] = s_g[0] * (a0 + be);
    g_partial[b][e][1 * D + h] = s_g[1] * (a1 + be);
    g_partial[b][e][2 * D + h] = s_g[2] * (a2 + be);
    g_partial[b][e][3 * D + h] = s_g[3] * (a3 + be);
}

// ---------------------------------------------------------------------------
// K3: combine experts, de-normalize, head matvec.  grid = 32 blocks, 128 thr
// ---------------------------------------------------------------------------
__global__ void k3_head(const float* __restrict__ W_head,
                        const float* __restrict__ b_head,
                        float* __restrict__ out) {
    const int b   = blockIdx.x;
    const int tid = threadIdx.x;

    __shared__ float s_t[LSEQ];

    const float mean = g_stats[b][0];
    const float std  = g_stats[b][1];

    for (int l = tid; l < LSEQ; l += 128) {
        float s = 0.f;
        #pragma unroll
        for (int e = 0; e < NE; e++) s += g_partial[b][e][l];
        s_t[l] = fmaf(s, std, mean);
    }
    __syncthreads();

    if (tid < PRED) {
        const float4* wr = reinterpret_cast<const float4*>(W_head + (size_t)tid * LSEQ);
        const float4* tt = reinterpret_cast<const float4*>(s_t);
        float ax = 0.f, ay = 0.f, az = 0.f, aw = 0.f;
        #pragma unroll 8
        for (int i = 0; i < LSEQ / 4; i++) {
            float4 w = wr[i];
            float4 f = tt[i];
            ax = fmaf(w.x, f.x, ax);
            ay = fmaf(w.y, f.y, ay);
            az = fmaf(w.z, f.z, az);
            aw = fmaf(w.w, f.w, aw);
        }
        out[b * PRED + tid] = (ax + ay) + (az + aw) + b_head[tid];
    }
}

// ---------------------------------------------------------------------------
extern "C" void kernel_launch(void* const* d_in, const int* in_sizes, int n_in,
                              void* d_out, int out_size) {
    const float* x         = (const float*)d_in[0];
    const float* W_proj    = (const float*)d_in[4];
    const float* b_proj    = (const float*)d_in[5];
    const float* W_router  = (const float*)d_in[6];
    const float* b_router  = (const float*)d_in[7];
    const float* W_experts = (const float*)d_in[8];
    const float* b_experts = (const float*)d_in[9];
    const float* W_head    = (const float*)d_in[10];
    const float* b_head    = (const float*)d_in[11];
    float* out = (float*)d_out;

    k1_prep<<<NB, 256>>>(x, W_proj, b_proj, W_router, b_router);
    k2_experts<<<NB * NE, 256>>>(W_experts, b_experts);
    k3_head<<<NB, 128>>>(W_head, b_head, out);
}

// round 2
// speedup vs baseline: 1.2583x; 1.2583x over previous
#include <cuda_runtime.h>
#include <math.h>

#define NB    32     // batch
#define LSEQ  1024
#define CH    34
#define D     256
#define NE    8
#define NP    4      // only first 4 patches survive the [:, :seq_len] slice
#define PL    16
#define PRED  96

// Scratch (device globals — no allocation allowed)
__device__ float g_stats[NB][2];              // mean, stdev
__device__ float g_partial[NB][NE][NP * D];   // gated expert partials

// ---------------------------------------------------------------------------
// K12: fused stats + patch projection + router + gated expert partials.
// grid = 256 blocks (b*8 + e), 256 threads.
// Each block redundantly computes b's stats/xp/gates (identical across the 8
// e-blocks -> deterministic), then does its expert's 4x256x256 matvec.
// ---------------------------------------------------------------------------
__global__ void k12_fused(const float* __restrict__ x,
                          const float* __restrict__ W_proj,
                          const float* __restrict__ b_proj,
                          const float* __restrict__ W_router,
                          const float* __restrict__ b_router,
                          const float* __restrict__ W_experts,
                          const float* __restrict__ b_experts) {
    const int b   = blockIdx.x >> 3;
    const int e   = blockIdx.x & 7;
    const int tid = threadIdx.x;

    __shared__ float s_wred[16];
    __shared__ float s_xn[NP * PL];       // 64 normalized inputs
    __shared__ float s_xp[NP * D];        // 4KB
    __shared__ float s_logit[NP * NE];
    __shared__ float s_g[NP];
    __shared__ float s_mean, s_inv;

    // ---- stats over x[b, :, 2] (1024 strided values, 4 per thread) ----
    const float* xb = x + (size_t)b * LSEQ * CH + 2;
    const float v0 = xb[(tid      ) * CH];
    const float v1 = xb[(tid + 256) * CH];
    const float v2 = xb[(tid + 512) * CH];
    const float v3 = xb[(tid + 768) * CH];
    float sum = v0 + v1 + v2 + v3;
    float sq  = v0*v0 + v1*v1 + v2*v2 + v3*v3;
    #pragma unroll
    for (int o = 16; o; o >>= 1) {
        sum += __shfl_xor_sync(0xffffffffu, sum, o);
        sq  += __shfl_xor_sync(0xffffffffu, sq,  o);
    }
    if ((tid & 31) == 0) { s_wred[tid >> 5] = sum; s_wred[8 + (tid >> 5)] = sq; }
    __syncthreads();
    if (tid == 0) {
        float ts = 0.f, tq = 0.f;
        #pragma unroll
        for (int w = 0; w < 8; w++) { ts += s_wred[w]; tq += s_wred[8 + w]; }
        const float mean = ts * (1.0f / LSEQ);
        const float var  = tq * (1.0f / LSEQ) - mean * mean;
        const float sd   = sqrtf(var + 1e-5f);
        s_mean = mean;
        s_inv  = 1.0f / sd;
        if (e == 0) { g_stats[b][0] = mean; g_stats[b][1] = sd; }
    }
    __syncthreads();

    if (tid < NP * PL) s_xn[tid] = (v0 - s_mean) * s_inv;   // l = tid < 64
    __syncthreads();

    // ---- xp[p][d], d = tid ----
    {
        const float* wr = W_proj + tid * PL;
        float w[PL];
        #pragma unroll
        for (int k = 0; k < PL; k++) w[k] = wr[k];
        const float bp = b_proj[tid];
        #pragma unroll
        for (int p = 0; p < NP; p++) {
            float acc = bp;
            #pragma unroll
            for (int k = 0; k < PL; k++) acc = fmaf(w[k], s_xn[p * PL + k], acc);
            s_xp[p * D + tid] = acc;
        }
    }
    __syncthreads();

    // ---- router logits (32 threads: p,e' pairs) ----
    if (tid < NP * NE) {
        const int p = tid >> 3, ee = tid & 7;
        const float* wr = W_router + ee * D;
        float acc = b_router[ee];
        #pragma unroll 8
        for (int d = 0; d < D; d++) acc = fmaf(wr[d], s_xp[p * D + d], acc);
        s_logit[tid] = acc;
    }
    __syncthreads();
    if (tid < NP) {
        float m = s_logit[tid * NE];
        #pragma unroll
        for (int j = 1; j < NE; j++) m = fmaxf(m, s_logit[tid * NE + j]);
        float denom = 0.f;
        #pragma unroll
        for (int j = 0; j < NE; j++) denom += __expf(s_logit[tid * NE + j] - m);
        s_g[tid] = __expf(s_logit[tid * NE + e] - m) / denom;
    }
    __syncthreads();

    // ---- gated expert matvec: thread h = tid, 4 patches reuse each W load ----
    const int h = tid;
    const float4* w4 = reinterpret_cast<const float4*>(
        W_experts + ((size_t)(e * D + h)) * D);
    const float4* x4 = reinterpret_cast<const float4*>(s_xp);

    float a0 = 0.f, a1 = 0.f, a2 = 0.f, a3 = 0.f;
    #pragma unroll 8
    for (int i = 0; i < D / 4; i++) {
        const float4 wv = w4[i];
        const float4 p0 = x4[0 * 64 + i];
        const float4 p1 = x4[1 * 64 + i];
        const float4 p2 = x4[2 * 64 + i];
        const float4 p3 = x4[3 * 64 + i];
        a0 = fmaf(wv.x, p0.x, a0); a0 = fmaf(wv.y, p0.y, a0);
        a0 = fmaf(wv.z, p0.z, a0); a0 = fmaf(wv.w, p0.w, a0);
        a1 = fmaf(wv.x, p1.x, a1); a1 = fmaf(wv.y, p1.y, a1);
        a1 = fmaf(wv.z, p1.z, a1); a1 = fmaf(wv.w, p1.w, a1);
        a2 = fmaf(wv.x, p2.x, a2); a2 = fmaf(wv.y, p2.y, a2);
        a2 = fmaf(wv.z, p2.z, a2); a2 = fmaf(wv.w, p2.w, a2);
        a3 = fmaf(wv.x, p3.x, a3); a3 = fmaf(wv.y, p3.y, a3);
        a3 = fmaf(wv.z, p3.z, a3); a3 = fmaf(wv.w, p3.w, a3);
    }
    const float be = b_experts[e * D + h];
    g_partial[b][e][0 * D + h] = s_g[0] * (a0 + be);
    g_partial[b][e][1 * D + h] = s_g[1] * (a1 + be);
    g_partial[b][e][2 * D + h] = s_g[2] * (a2 + be);
    g_partial[b][e][3 * D + h] = s_g[3] * (a3 + be);
}

// ---------------------------------------------------------------------------
// K3: combine experts, de-normalize, head matvec.
// grid = 32 blocks, 256 threads. 2 lanes per output row + shfl combine.
// ---------------------------------------------------------------------------
__global__ void k3_head(const float* __restrict__ W_head,
                        const float* __restrict__ b_head,
                        float* __restrict__ out) {
    const int b   = blockIdx.x;
    const int tid = threadIdx.x;

    __shared__ float s_t[LSEQ];

    const float mean = g_stats[b][0];
    const float sd   = g_stats[b][1];

    // expert sum + de-normalize: thread handles 4 consecutive l via float4
    {
        float4 acc = make_float4(0.f, 0.f, 0.f, 0.f);
        #pragma unroll
        for (int e = 0; e < NE; e++) {
            const float4 v = reinterpret_cast<const float4*>(g_partial[b][e])[tid];
            acc.x += v.x; acc.y += v.y; acc.z += v.z; acc.w += v.w;
        }
        reinterpret_cast<float4*>(s_t)[tid] =
            make_float4(fmaf(acc.x, sd, mean), fmaf(acc.y, sd, mean),
                        fmaf(acc.z, sd, mean), fmaf(acc.w, sd, mean));
    }
    __syncthreads();

    // head matvec: (t, half) per thread, 128 float4 iterations, shfl combine
    if (tid < 2 * PRED) {
        const int t    = tid >> 1;
        const int half = tid & 1;
        const float4* wr = reinterpret_cast<const float4*>(
            W_head + (size_t)t * LSEQ + half * (LSEQ / 2));
        const float4* tt = reinterpret_cast<const float4*>(s_t + half * (LSEQ / 2));
        float ax = 0.f, ay = 0.f, az = 0.f, aw = 0.f;
        #pragma unroll 8
        for (int i = 0; i < LSEQ / 8; i++) {
            const float4 w = wr[i];
            const float4 f = tt[i];
            ax = fmaf(w.x, f.x, ax);
            ay = fmaf(w.y, f.y, ay);
            az = fmaf(w.z, f.z, az);
            aw = fmaf(w.w, f.w, aw);
        }
        float r = (ax + ay) + (az + aw);
        r += __shfl_xor_sync(0xffffffffu, r, 1);
        if (half == 0) out[b * PRED + t] = r + b_head[t];
    }
}

// ---------------------------------------------------------------------------
extern "C" void kernel_launch(void* const* d_in, const int* in_sizes, int n_in,
                              void* d_out, int out_size) {
    const float* x         = (const float*)d_in[0];
    const float* W_proj    = (const float*)d_in[4];
    const float* b_proj    = (const float*)d_in[5];
    const float* W_router  = (const float*)d_in[6];
    const float* b_router  = (const float*)d_in[7];
    const float* W_experts = (const float*)d_in[8];
    const float* b_experts = (const float*)d_in[9];
    const float* W_head    = (const float*)d_in[10];
    const float* b_head    = (const float*)d_in[11];
    float* out = (float*)d_out;

    k12_fused<<<NB * NE, 256>>>(x, W_proj, b_proj, W_router, b_router,
                                W_experts, b_experts);
    k3_head<<<NB, 256>>>(W_head, b_head, out);
}

// round 4
// speedup vs baseline: 1.4579x; 1.1586x over previous
#include <cuda_runtime.h>
#include <math.h>

#define NB    32     // batch
#define LSEQ  1024
#define CH    34
#define D     256
#define NE    8
#define NP    4      // only first 4 patches survive the [:, :seq_len] slice
#define PL    16
#define PRED  96

// Scratch (device globals — no allocation allowed)
__device__ float g_stats[NB][2];              // mean, stdev
__device__ float g_partial[NB][NE][NP * D];   // gated expert partials

// ---------------------------------------------------------------------------
// K12: fused stats + patch projection + router + gated expert partials.
// grid = 256 blocks (b*8 + e), 512 threads.
// Expert matvec: thread = (h, d-half); 512 FMAs each; shfl pair-combine.
// ---------------------------------------------------------------------------
__global__ void __launch_bounds__(512)
k12_fused(const float* __restrict__ x,
          const float* __restrict__ W_proj,
          const float* __restrict__ b_proj,
          const float* __restrict__ W_router,
          const float* __restrict__ b_router,
          const float* __restrict__ W_experts,
          const float* __restrict__ b_experts) {
    const int b   = blockIdx.x >> 3;
    const int e   = blockIdx.x & 7;
    const int tid = threadIdx.x;

    __shared__ float s_wred[32];
    __shared__ float s_xn[NP * PL];       // 64 normalized inputs
    __shared__ float s_xp[NP * D];        // 4KB
    __shared__ float s_logit[NP * NE];
    __shared__ float s_g[NP];
    __shared__ float s_mean, s_inv;

    // ---- stats over x[b, :, 2] (1024 strided values, 2 per thread) ----
    const float* xb = x + (size_t)b * LSEQ * CH + 2;
    const float v0 = xb[(tid      ) * CH];
    const float v1 = xb[(tid + 512) * CH];
    float sum = v0 + v1;
    float sq  = v0 * v0 + v1 * v1;
    #pragma unroll
    for (int o = 16; o; o >>= 1) {
        sum += __shfl_xor_sync(0xffffffffu, sum, o);
        sq  += __shfl_xor_sync(0xffffffffu, sq,  o);
    }
    if ((tid & 31) == 0) { s_wred[tid >> 5] = sum; s_wred[16 + (tid >> 5)] = sq; }
    __syncthreads();
    if (tid == 0) {
        float ts = 0.f, tq = 0.f;
        #pragma unroll
        for (int w = 0; w < 16; w++) { ts += s_wred[w]; tq += s_wred[16 + w]; }
        const float mean = ts * (1.0f / LSEQ);
        const float var  = tq * (1.0f / LSEQ) - mean * mean;
        const float sd   = sqrtf(var + 1e-5f);
        s_mean = mean;
        s_inv  = 1.0f / sd;
        if (e == 0) { g_stats[b][0] = mean; g_stats[b][1] = sd; }
    }
    __syncthreads();

    if (tid < NP * PL) s_xn[tid] = (v0 - s_mean) * s_inv;   // l = tid < 64
    __syncthreads();

    // ---- xp[p][d]: d = tid&255, patch pair = tid>>8 ----
    {
        const int d  = tid & 255;
        const int pg = tid >> 8;            // 0 -> p{0,1}, 1 -> p{2,3}
        const float* wr = W_proj + d * PL;
        float w[PL];
        #pragma unroll
        for (int k = 0; k < PL; k++) w[k] = wr[k];
        const float bp = b_proj[d];
        #pragma unroll
        for (int pp = 0; pp < 2; pp++) {
            const int p = pg * 2 + pp;
            float acc = bp;
            #pragma unroll
            for (int k = 0; k < PL; k++) acc = fmaf(w[k], s_xn[p * PL + k], acc);
            s_xp[p * D + d] = acc;
        }
    }
    __syncthreads();

    // ---- router logits (32 threads: p,e' pairs) ----
    if (tid < NP * NE) {
        const int p = tid >> 3, ee = tid & 7;
        const float* wr = W_router + ee * D;
        float acc = b_router[ee];
        #pragma unroll 8
        for (int d = 0; d < D; d++) acc = fmaf(wr[d], s_xp[p * D + d], acc);
        s_logit[tid] = acc;
    }
    __syncthreads();
    if (tid < NP) {
        float m = s_logit[tid * NE];
        #pragma unroll
        for (int j = 1; j < NE; j++) m = fmaxf(m, s_logit[tid * NE + j]);
        float denom = 0.f;
        #pragma unroll
        for (int j = 0; j < NE; j++) denom += __expf(s_logit[tid * NE + j] - m);
        s_g[tid] = __expf(s_logit[tid * NE + e] - m) / denom;
    }
    __syncthreads();

    // ---- gated expert matvec: thread = (h, dhalf), 32 float4 W loads ----
    const int h  = tid >> 1;
    const int dh = tid & 1;
    const float4* w4 = reinterpret_cast<const float4*>(
        W_experts + ((size_t)(e * D + h)) * D + dh * (D / 2));
    const float4* x4 = reinterpret_cast<const float4*>(s_xp) + dh * 32;

    float a0 = 0.f, a1 = 0.f, a2 = 0.f, a3 = 0.f;
    #pragma unroll 16
    for (int i = 0; i < D / 8; i++) {
        const float4 wv = w4[i];
        const float4 p0 = x4[0 * 64 + i];
        const float4 p1 = x4[1 * 64 + i];
        const float4 p2 = x4[2 * 64 + i];
        const float4 p3 = x4[3 * 64 + i];
        a0 = fmaf(wv.x, p0.x, a0); a0 = fmaf(wv.y, p0.y, a0);
        a0 = fmaf(wv.z, p0.z, a0); a0 = fmaf(wv.w, p0.w, a0);
        a1 = fmaf(wv.x, p1.x, a1); a1 = fmaf(wv.y, p1.y, a1);
        a1 = fmaf(wv.z, p1.z, a1); a1 = fmaf(wv.w, p1.w, a1);
        a2 = fmaf(wv.x, p2.x, a2); a2 = fmaf(wv.y, p2.y, a2);
        a2 = fmaf(wv.z, p2.z, a2); a2 = fmaf(wv.w, p2.w, a2);
        a3 = fmaf(wv.x, p3.x, a3); a3 = fmaf(wv.y, p3.y, a3);
        a3 = fmaf(wv.z, p3.z, a3); a3 = fmaf(wv.w, p3.w, a3);
    }
    // combine the two d-halves (pair lanes dh=0/1)
    a0 += __shfl_xor_sync(0xffffffffu, a0, 1);
    a1 += __shfl_xor_sync(0xffffffffu, a1, 1);
    a2 += __shfl_xor_sync(0xffffffffu, a2, 1);
    a3 += __shfl_xor_sync(0xffffffffu, a3, 1);

    if (dh == 0) {
        const float be = b_experts[e * D + h];
        g_partial[b][e][0 * D + h] = s_g[0] * (a0 + be);
        g_partial[b][e][1 * D + h] = s_g[1] * (a1 + be);
        g_partial[b][e][2 * D + h] = s_g[2] * (a2 + be);
        g_partial[b][e][3 * D + h] = s_g[3] * (a3 + be);
    }
}

// ---------------------------------------------------------------------------
// K3: combine experts, de-normalize, head matvec.
// grid = (32 b, 12 t-tiles), 256 threads. 8 warps -> 8 outputs per block.
// ---------------------------------------------------------------------------
__global__ void __launch_bounds__(256)
k3_head(const float* __restrict__ W_head,
        const float* __restrict__ b_head,
        float* __restrict__ out) {
    const int b    = blockIdx.x;
    const int tid  = threadIdx.x;
    const int warp = tid >> 5;
    const int lane = tid & 31;

    __shared__ float s_t[LSEQ];

    const float mean = g_stats[b][0];
    const float sd   = g_stats[b][1];

    // expert sum + de-normalize: thread handles 4 consecutive l via float4
    {
        float4 acc = make_float4(0.f, 0.f, 0.f, 0.f);
        #pragma unroll
        for (int e = 0; e < NE; e++) {
            const float4 v = reinterpret_cast<const float4*>(g_partial[b][e])[tid];
            acc.x += v.x; acc.y += v.y; acc.z += v.z; acc.w += v.w;
        }
        reinterpret_cast<float4*>(s_t)[tid] =
            make_float4(fmaf(acc.x, sd, mean), fmaf(acc.y, sd, mean),
                        fmaf(acc.z, sd, mean), fmaf(acc.w, sd, mean));
    }
    __syncthreads();

    // one output t per warp; lanes stride the 256 float4s of the row
    const int t = blockIdx.y * 8 + warp;
    const float4* wr = reinterpret_cast<const float4*>(W_head + (size_t)t * LSEQ);
    const float4* tt = reinterpret_cast<const float4*>(s_t);
    float ax = 0.f, ay = 0.f, az = 0.f, aw = 0.f;
    #pragma unroll
    for (int j = 0; j < LSEQ / 4 / 32; j++) {
        const int i = j * 32 + lane;
        const float4 w = wr[i];
        const float4 f = tt[i];
        ax = fmaf(w.x, f.x, ax);
        ay = fmaf(w.y, f.y, ay);
        az = fmaf(w.z, f.z, az);
        aw = fmaf(w.w, f.w, aw);
    }
    float r = (ax + ay) + (az + aw);
    #pragma unroll
    for (int o = 16; o; o >>= 1) r += __shfl_xor_sync(0xffffffffu, r, o);
    if (lane == 0) out[b * PRED + t] = r + b_head[t];
}

// ---------------------------------------------------------------------------
extern "C" void kernel_launch(void* const* d_in, const int* in_sizes, int n_in,
                              void* d_out, int out_size) {
    const float* x         = (const float*)d_in[0];
    const float* W_proj    = (const float*)d_in[4];
    const float* b_proj    = (const float*)d_in[5];
    const float* W_router  = (const float*)d_in[6];
    const float* b_router  = (const float*)d_in[7];
    const float* W_experts = (const float*)d_in[8];
    const float* b_experts = (const float*)d_in[9];
    const float* W_head    = (const float*)d_in[10];
    const float* b_head    = (const float*)d_in[11];
    float* out = (float*)d_out;

    k12_fused<<<NB * NE, 512>>>(x, W_proj, b_proj, W_router, b_router,
                                W_experts, b_experts);
    dim3 g3(NB, PRED / 8);
    k3_head<<<g3, 256>>>(W_head, b_head, out);
}

// round 6
// speedup vs baseline: 2.9733x; 2.0394x over previous
#include <cuda_runtime.h>
#include <math.h>

#define NB    32     // batch
#define LSEQ  1024
#define CH    34
#define D     256
#define NE    8
#define NP    4      // only first 4 patches survive the [:, :seq_len] slice
#define PL    16
#define PRED  96

// Scratch (device globals — no allocation allowed). 16B-aligned for float4 IO.
__device__ float g_stats[NB][2];
__device__ __align__(16) float g_xp[NB][NP][D];
__device__ __align__(16) float g_gates[NB][NP][NE];
__device__ __align__(16) float g_partial[NB][NE][NP * D];

// ---------------------------------------------------------------------------
// K1: per-b stats + patch projection + router gates.  grid=32, 512 threads.
// ---------------------------------------------------------------------------
__global__ void __launch_bounds__(512)
k1_prep(const float* __restrict__ x,
        const float* __restrict__ W_proj,
        const float* __restrict__ b_proj,
        const float* __restrict__ W_router,
        const float* __restrict__ b_router) {
    const int b    = blockIdx.x;
    const int tid  = threadIdx.x;
    const int warp = tid >> 5;
    const int lane = tid & 31;

    __shared__ float s_wred[32];
    __shared__ __align__(16) float s_xn[NP * PL];
    __shared__ __align__(16) float s_xp[NP * D];
    __shared__ float s_logit[NP * NE];
    __shared__ float s_mean, s_inv;

    // ---- stats over x[b, :, 2] ----
    const float* xb = x + (size_t)b * LSEQ * CH + 2;
    const float v0 = xb[(tid      ) * CH];
    const float v1 = xb[(tid + 512) * CH];
    float sum = v0 + v1;
    float sq  = v0 * v0 + v1 * v1;
    #pragma unroll
    for (int o = 16; o; o >>= 1) {
        sum += __shfl_xor_sync(0xffffffffu, sum, o);
        sq  += __shfl_xor_sync(0xffffffffu, sq,  o);
    }
    if (lane == 0) { s_wred[warp] = sum; s_wred[16 + warp] = sq; }
    __syncthreads();
    if (tid == 0) {
        float ts = 0.f, tq = 0.f;
        #pragma unroll
        for (int w = 0; w < 16; w++) { ts += s_wred[w]; tq += s_wred[16 + w]; }
        const float mean = ts * (1.0f / LSEQ);
        const float var  = tq * (1.0f / LSEQ) - mean * mean;
        const float sd   = sqrtf(var + 1e-5f);
        s_mean = mean; s_inv = 1.0f / sd;
        g_stats[b][0] = mean; g_stats[b][1] = sd;
    }
    __syncthreads();

    if (tid < NP * PL) s_xn[tid] = (v0 - s_mean) * s_inv;   // l = tid < 64
    __syncthreads();

    // ---- xp[p][d]: d = tid&255, patch pair = tid>>8 ----
    {
        const int d  = tid & 255;
        const int pg = tid >> 8;
        const float* wr = W_proj + d * PL;
        float w[PL];
        #pragma unroll
        for (int k = 0; k < PL; k++) w[k] = wr[k];
        const float bp = b_proj[d];
        #pragma unroll
        for (int pp = 0; pp < 2; pp++) {
            const int p = pg * 2 + pp;
            float acc = bp;
            #pragma unroll
            for (int k = 0; k < PL; k++) acc = fmaf(w[k], s_xn[p * PL + k], acc);
            s_xp[p * D + d] = acc;
        }
    }
    __syncthreads();

    // publish xp to global (float4)
    if (tid < NP * D / 4) {
        reinterpret_cast<float4*>(&g_xp[b][0][0])[tid] =
            reinterpret_cast<const float4*>(s_xp)[tid];
    }

    // ---- router logits: warp-parallel; warp handles pairs w and w+16 ----
    #pragma unroll
    for (int it = 0; it < 2; it++) {
        const int pi = warp + 16 * it;          // pi = p*8 + e
        const int p  = pi >> 3, e = pi & 7;
        const float* wr = W_router + e * D;
        float acc = 0.f;
        #pragma unroll
        for (int q = 0; q < D / 32; q++) {
            const int d = lane + q * 32;
            acc = fmaf(wr[d], s_xp[p * D + d], acc);
        }
        #pragma unroll
        for (int o = 16; o; o >>= 1) acc += __shfl_xor_sync(0xffffffffu, acc, o);
        if (lane == 0) s_logit[pi] = acc + b_router[e];
    }
    __syncthreads();

    if (tid < NP) {
        const int p = tid;
        float m = s_logit[p * NE];
        #pragma unroll
        for (int j = 1; j < NE; j++) m = fmaxf(m, s_logit[p * NE + j]);
        float denom = 0.f;
        float ex[NE];
        #pragma unroll
        for (int j = 0; j < NE; j++) { ex[j] = __expf(s_logit[p * NE + j] - m); denom += ex[j]; }
        const float inv = 1.0f / denom;
        #pragma unroll
        for (int j = 0; j < NE; j++) g_gates[b][p][j] = ex[j] * inv;
    }
}

// ---------------------------------------------------------------------------
// K2: per-expert smem GEMM.  grid = (8 e, 4 b-tiles, 4 h-tiles), 256 threads.
// Block: M = 32 rows (8 b x 4 p), N = 64 h, K = 256.
// Thread: 4 rows x 4 strided h (h = ht + 16j) x K-half; shfl pair-combine.
// ---------------------------------------------------------------------------
#define K2_SMEM_BYTES ((64 * 65 + 32 * 65) * 16 + 32 * 4 + 64 * 4)

__global__ void __launch_bounds__(256)
k2_experts(const float* __restrict__ W_experts,
           const float* __restrict__ b_experts) {
    extern __shared__ float4 smem4[];
    float4* s_w  = smem4;                       // 64 rows x 65 float4
    float4* s_xp = smem4 + 64 * 65;             // 32 rows x 65 float4
    float*  s_g  = (float*)(smem4 + 96 * 65);   // 32 gates
    float*  s_be = s_g + 32;                    // 64 biases

    const int e   = blockIdx.x;
    const int bt  = blockIdx.y;                 // 8 b per tile
    const int htb = blockIdx.z;                 // 64 h per tile
    const int tid = threadIdx.x;

    // cooperative load: W slice (coalesced, 16 float4/thread)
    const float4* Wg = reinterpret_cast<const float4*>(W_experts);
    #pragma unroll
    for (int r = 0; r < 16; r++) {
        const int flat = r * 256 + tid;         // 0..4095
        const int row = flat >> 6, col = flat & 63;
        s_w[row * 65 + col] = Wg[(size_t)(e * D + htb * 64 + row) * 64 + col];
    }
    // cooperative load: xp rows (8 b x 4 p = 32 rows)
    const float4* Xg = reinterpret_cast<const float4*>(g_xp);
    #pragma unroll
    for (int r = 0; r < 8; r++) {
        const int flat = r * 256 + tid;         // 0..2047
        const int row = flat >> 6, col = flat & 63;
        s_xp[row * 65 + col] = Xg[(bt * 8 * NP + row) * 64 + col];
    }
    if (tid < 32) {
        const int bl = tid >> 2, p = tid & 3;
        s_g[tid] = g_gates[bt * 8 + bl][p][e];
    }
    if (tid < 64) s_be[tid] = b_experts[e * D + htb * 64 + tid];
    __syncthreads();

    const int kh = tid & 1;                 // K half
    const int ht = (tid >> 1) & 15;         // h base (strided tile)
    const int rt = tid >> 5;                // row tile (warp-constant)

    float acc[4][4];
    #pragma unroll
    for (int i = 0; i < 4; i++)
        #pragma unroll
        for (int j = 0; j < 4; j++) acc[i][j] = 0.f;

    const float4* xb4 = s_xp + rt * 4 * 65 + kh * 32;
    const float4* wb4 = s_w  + ht * 65     + kh * 32;

    #pragma unroll 4
    for (int kk = 0; kk < 32; kk++) {
        const float4 x0 = xb4[0 * 65 + kk];
        const float4 x1 = xb4[1 * 65 + kk];
        const float4 x2 = xb4[2 * 65 + kk];
        const float4 x3 = xb4[3 * 65 + kk];
        const float4 w0 = wb4[0 * 1040 + kk];
        const float4 w1 = wb4[1 * 1040 + kk];
        const float4 w2 = wb4[2 * 1040 + kk];
        const float4 w3 = wb4[3 * 1040 + kk];
        #pragma unroll
        for (int i = 0; i < 4; i++) {
            const float4 xv = (i == 0) ? x0 : (i == 1) ? x1 : (i == 2) ? x2 : x3;
            acc[i][0] = fmaf(xv.x, w0.x, acc[i][0]); acc[i][0] = fmaf(xv.y, w0.y, acc[i][0]);
            acc[i][0] = fmaf(xv.z, w0.z, acc[i][0]); acc[i][0] = fmaf(xv.w, w0.w, acc[i][0]);
            acc[i][1] = fmaf(xv.x, w1.x, acc[i][1]); acc[i][1] = fmaf(xv.y, w1.y, acc[i][1]);
            acc[i][1] = fmaf(xv.z, w1.z, acc[i][1]); acc[i][1] = fmaf(xv.w, w1.w, acc[i][1]);
            acc[i][2] = fmaf(xv.x, w2.x, acc[i][2]); acc[i][2] = fmaf(xv.y, w2.y, acc[i][2]);
            acc[i][2] = fmaf(xv.z, w2.z, acc[i][2]); acc[i][2] = fmaf(xv.w, w2.w, acc[i][2]);
            acc[i][3] = fmaf(xv.x, w3.x, acc[i][3]); acc[i][3] = fmaf(xv.y, w3.y, acc[i][3]);
            acc[i][3] = fmaf(xv.z, w3.z, acc[i][3]); acc[i][3] = fmaf(xv.w, w3.w, acc[i][3]);
        }
    }

    // combine the two K halves (lane pairs kh=0/1)
    #pragma unroll
    for (int i = 0; i < 4; i++)
        #pragma unroll
        for (int j = 0; j < 4; j++)
            acc[i][j] += __shfl_xor_sync(0xffffffffu, acc[i][j], 1);

    if (kh == 0) {
        #pragma unroll
        for (int i = 0; i < 4; i++) {
            const int r = rt * 4 + i;
            const int b = bt * 8 + (r >> 2);
            const int p = r & 3;
            const float g = s_g[r];
            #pragma unroll
            for (int j = 0; j < 4; j++) {
                const int hl = ht + j * 16;
                g_partial[b][e][p * D + htb * 64 + hl] = g * (acc[i][j] + s_be[hl]);
            }
        }
    }
}

// ---------------------------------------------------------------------------
// K3: combine experts, de-normalize, head matvec.
// grid = (32 b, 24 t-tiles), 128 threads; 4 warps -> 4 outputs per block.
// ---------------------------------------------------------------------------
__global__ void __launch_bounds__(128)
k3_head(const float* __restrict__ W_head,
        const float* __restrict__ b_head,
        float* __restrict__ out) {
    const int b    = blockIdx.x;
    const int tid  = threadIdx.x;
    const int warp = tid >> 5;
    const int lane = tid & 31;

    __shared__ __align__(16) float s_t[LSEQ];

    const float mean = g_stats[b][0];
    const float sd   = g_stats[b][1];

    // expert sum + de-normalize: 2 float4 per thread
    const float4* gp = reinterpret_cast<const float4*>(&g_partial[b][0][0]);
    #pragma unroll
    for (int c = 0; c < 2; c++) {
        const int i = tid + c * 128;        // float4 index 0..255
        float4 acc = make_float4(0.f, 0.f, 0.f, 0.f);
        #pragma unroll
        for (int e = 0; e < NE; e++) {
            const float4 v = gp[e * 256 + i];
            acc.x += v.x; acc.y += v.y; acc.z += v.z; acc.w += v.w;
        }
        reinterpret_cast<float4*>(s_t)[i] =
            make_float4(fmaf(acc.x, sd, mean), fmaf(acc.y, sd, mean),
                        fmaf(acc.z, sd, mean), fmaf(acc.w, sd, mean));
    }
    __syncthreads();

    // one output t per warp
    const int t = blockIdx.y * 4 + warp;
    const float4* wr = reinterpret_cast<const float4*>(W_head + (size_t)t * LSEQ);
    const float4* tt = reinterpret_cast<const float4*>(s_t);
    float ax = 0.f, ay = 0.f, az = 0.f, aw = 0.f;
    #pragma unroll
    for (int q = 0; q < 8; q++) {
        const int i = q * 32 + lane;
        const float4 w = wr[i];
        const float4 f = tt[i];
        ax = fmaf(w.x, f.x, ax);
        ay = fmaf(w.y, f.y, ay);
        az = fmaf(w.z, f.z, az);
        aw = fmaf(w.w, f.w, aw);
    }
    float r = (ax + ay) + (az + aw);
    #pragma unroll
    for (int o = 16; o; o >>= 1) r += __shfl_xor_sync(0xffffffffu, r, o);
    if (lane == 0) out[b * PRED + t] = r + b_head[t];
}

// ---------------------------------------------------------------------------
extern "C" void kernel_launch(void* const* d_in, const int* in_sizes, int n_in,
                              void* d_out, int out_size) {
    const float* x         = (const float*)d_in[0];
    const float* W_proj    = (const float*)d_in[4];
    const float* b_proj    = (const float*)d_in[5];
    const float* W_router  = (const float*)d_in[6];
    const float* b_router  = (const float*)d_in[7];
    const float* W_experts = (const float*)d_in[8];
    const float* b_experts = (const float*)d_in[9];
    const float* W_head    = (const float*)d_in[10];
    const float* b_head    = (const float*)d_in[11];
    float* out = (float*)d_out;

    cudaFuncSetAttribute(k2_experts,
                         cudaFuncAttributeMaxDynamicSharedMemorySize,
                         K2_SMEM_BYTES);

    k1_prep<<<NB, 512>>>(x, W_proj, b_proj, W_router, b_router);
    dim3 g2(NE, NB / 8, NP);     // 8 x 4 x 4 = 128 blocks
    k2_experts<<<g2, 256, K2_SMEM_BYTES>>>(W_experts, b_experts);
    dim3 g3(NB, PRED / 4);       // 32 x 24 = 768 blocks
    k3_head<<<g3, 128>>>(W_head, b_head, out);
}

// round 8
// speedup vs baseline: 3.2275x; 1.0855x over previous
#include <cuda_runtime.h>
#include <math.h>

#define NB    32     // batch
#define LSEQ  1024
#define CH    34
#define D     256
#define NE    8
#define NP    4      // only first 4 patches survive the [:, :seq_len] slice
#define PL    16
#define PRED  96

// Scratch (device globals — no allocation allowed). 16B-aligned for float4 IO.
__device__ float g_stats[NB][2];
__device__ float g_red[NB][8][2];             // per-segment partial sums
__device__ float g_sink[4];                   // dead store target (never read)
__device__ __align__(16) float g_xp[NB][NP][D];
__device__ __align__(16) float g_gates[NB][NP][NE];
__device__ __align__(16) float g_partial[NB][NE][NP * D];

// ---------------------------------------------------------------------------
// K0: wide partial stats over x[b,:,2] + L2 warm of W_experts / W_head.
// grid = 256 blocks (b*8 + seg), 128 threads.
// ---------------------------------------------------------------------------
__global__ void __launch_bounds__(128)
k0_stats(const float* __restrict__ x,
         const float* __restrict__ W_experts,
         const float* __restrict__ W_head) {
    const int blk = blockIdx.x;
    const int b   = blk >> 3;
    const int seg = blk & 7;
    const int tid  = threadIdx.x;
    const int warp = tid >> 5;
    const int lane = tid & 31;

    __shared__ float sred[8];

    const float v = x[(size_t)b * LSEQ * CH + (size_t)(seg * 128 + tid) * CH + 2];

    // L2 warm (independent loads, overlap with x latency)
    float acc = 0.f;
    {
        const float4* we4 = reinterpret_cast<const float4*>(W_experts);
        #pragma unroll
        for (int i = 0; i < 4; i++) {
            const float4 t = we4[(size_t)blk * 512 + i * 128 + tid];
            acc += t.x + t.y + t.z + t.w;
        }
        if (tid < 96) {
            const float4 t = reinterpret_cast<const float4*>(W_head)[(size_t)blk * 96 + tid];
            acc += t.x + t.y + t.z + t.w;
        }
    }

    float sum = v, sq = v * v;
    #pragma unroll
    for (int o = 16; o; o >>= 1) {
        sum += __shfl_xor_sync(0xffffffffu, sum, o);
        sq  += __shfl_xor_sync(0xffffffffu, sq,  o);
    }
    if (lane == 0) { sred[warp] = sum; sred[4 + warp] = sq; }
    __syncthreads();
    if (tid == 0) {
        g_red[b][seg][0] = (sred[0] + sred[1]) + (sred[2] + sred[3]);
        g_red[b][seg][1] = (sred[4] + sred[5]) + (sred[6] + sred[7]);
    }
    // keep the warm loads alive; never fires on finite inputs (deterministic)
    if (acc != acc) g_sink[0] = acc;
}

// ---------------------------------------------------------------------------
// K1b: finalize stats + patch projection + router gates. grid=32, 256 thr.
// ---------------------------------------------------------------------------
__global__ void __launch_bounds__(256)
k1_prep(const float* __restrict__ x,
        const float* __restrict__ W_proj,
        const float* __restrict__ b_proj,
        const float* __restrict__ W_router,
        const float* __restrict__ b_router) {
    const int b    = blockIdx.x;
    const int tid  = threadIdx.x;
    const int warp = tid >> 5;
    const int lane = tid & 31;

    __shared__ __align__(16) float s_xn[NP * PL];
    __shared__ __align__(16) float s_xp[NP * D];
    __shared__ float s_logit[NP * NE];
    __shared__ float s_mean, s_inv;

    // early independent load: first 64 values of x[b,:,2]
    float v = 0.f;
    if (tid < NP * PL)
        v = x[(size_t)b * LSEQ * CH + (size_t)tid * CH + 2];

    if (tid == 0) {
        float ts = 0.f, tq = 0.f;
        #pragma unroll
        for (int s = 0; s < 8; s++) { ts += g_red[b][s][0]; tq += g_red[b][s][1]; }
        const float mean = ts * (1.0f / LSEQ);
        const float var  = tq * (1.0f / LSEQ) - mean * mean;
        const float sd   = sqrtf(var + 1e-5f);
        s_mean = mean; s_inv = 1.0f / sd;
        g_stats[b][0] = mean; g_stats[b][1] = sd;
    }
    __syncthreads();

    if (tid < NP * PL) s_xn[tid] = (v - s_mean) * s_inv;
    __syncthreads();

    // ---- xp[p][d], d = tid ----
    {
        const float4* wr4 = reinterpret_cast<const float4*>(W_proj + tid * PL);
        float w[PL];
        #pragma unroll
        for (int q = 0; q < 4; q++) {
            const float4 t = wr4[q];
            w[q * 4 + 0] = t.x; w[q * 4 + 1] = t.y; w[q * 4 + 2] = t.z; w[q * 4 + 3] = t.w;
        }
        const float bp = b_proj[tid];
        #pragma unroll
        for (int p = 0; p < NP; p++) {
            float acc = bp;
            #pragma unroll
            for (int k = 0; k < PL; k++) acc = fmaf(w[k], s_xn[p * PL + k], acc);
            s_xp[p * D + tid] = acc;
        }
    }
    __syncthreads();

    // publish xp (float4)
    reinterpret_cast<float4*>(&g_xp[b][0][0])[tid] =
        reinterpret_cast<const float4*>(s_xp)[tid & 255];

    // ---- router logits: 8 warps x 4 pi each ----
    #pragma unroll
    for (int r = 0; r < 4; r++) {
        const int pi = warp * 4 + r;            // pi = p*8 + e
        const int p  = pi >> 3, e = pi & 7;
        const float* wr = W_router + e * D;
        float acc = 0.f;
        #pragma unroll
        for (int q = 0; q < D / 32; q++) {
            const int d = lane + q * 32;
            acc = fmaf(wr[d], s_xp[p * D + d], acc);
        }
        #pragma unroll
        for (int o = 16; o; o >>= 1) acc += __shfl_xor_sync(0xffffffffu, acc, o);
        if (lane == 0) s_logit[pi] = acc + b_router[e];
    }
    __syncthreads();

    if (tid < NP) {
        const int p = tid;
        float m = s_logit[p * NE];
        #pragma unroll
        for (int j = 1; j < NE; j++) m = fmaxf(m, s_logit[p * NE + j]);
        float denom = 0.f;
        float ex[NE];
        #pragma unroll
        for (int j = 0; j < NE; j++) { ex[j] = __expf(s_logit[p * NE + j] - m); denom += ex[j]; }
        const float inv = 1.0f / denom;
        #pragma unroll
        for (int j = 0; j < NE; j++) g_gates[b][p][j] = ex[j] * inv;
    }
}

// ---------------------------------------------------------------------------
// K2: per-expert smem GEMM.  grid = (8 e, 4 b-tiles, 4 h-tiles), 256 threads.
// ---------------------------------------------------------------------------
#define K2_SMEM_BYTES ((64 * 65 + 32 * 65) * 16 + 32 * 4 + 64 * 4)

__global__ void __launch_bounds__(256)
k2_experts(const float* __restrict__ W_experts,
           const float* __restrict__ b_experts) {
    extern __shared__ float4 smem4[];
    float4* s_w  = smem4;                       // 64 rows x 65 float4
    float4* s_xp = smem4 + 64 * 65;             // 32 rows x 65 float4
    float*  s_g  = (float*)(smem4 + 96 * 65);   // 32 gates
    float*  s_be = s_g + 32;                    // 64 biases

    const int e   = blockIdx.x;
    const int bt  = blockIdx.y;
    const int htb = blockIdx.z;
    const int tid = threadIdx.x;

    const float4* Wg = reinterpret_cast<const float4*>(W_experts);
    #pragma unroll
    for (int r = 0; r < 16; r++) {
        const int flat = r * 256 + tid;
        const int row = flat >> 6, col = flat & 63;
        s_w[row * 65 + col] = Wg[(size_t)(e * D + htb * 64 + row) * 64 + col];
    }
    const float4* Xg = reinterpret_cast<const float4*>(g_xp);
    #pragma unroll
    for (int r = 0; r < 8; r++) {
        const int flat = r * 256 + tid;
        const int row = flat >> 6, col = flat & 63;
        s_xp[row * 65 + col] = Xg[(bt * 8 * NP + row) * 64 + col];
    }
    if (tid < 32) {
        const int bl = tid >> 2, p = tid & 3;
        s_g[tid] = g_gates[bt * 8 + bl][p][e];
    }
    if (tid < 64) s_be[tid] = b_experts[e * D + htb * 64 + tid];
    __syncthreads();

    const int kh = tid & 1;
    const int ht = (tid >> 1) & 15;
    const int rt = tid >> 5;

    float acc[4][4];
    #pragma unroll
    for (int i = 0; i < 4; i++)
        #pragma unroll
        for (int j = 0; j < 4; j++) acc[i][j] = 0.f;

    const float4* xb4 = s_xp + rt * 4 * 65 + kh * 32;
    const float4* wb4 = s_w  + ht * 65     + kh * 32;

    #pragma unroll 4
    for (int kk = 0; kk < 32; kk++) {
        const float4 x0 = xb4[0 * 65 + kk];
        const float4 x1 = xb4[1 * 65 + kk];
        const float4 x2 = xb4[2 * 65 + kk];
        const float4 x3 = xb4[3 * 65 + kk];
        const float4 w0 = wb4[0 * 1040 + kk];
        const float4 w1 = wb4[1 * 1040 + kk];
        const float4 w2 = wb4[2 * 1040 + kk];
        const float4 w3 = wb4[3 * 1040 + kk];
        #pragma unroll
        for (int i = 0; i < 4; i++) {
            const float4 xv = (i == 0) ? x0 : (i == 1) ? x1 : (i == 2) ? x2 : x3;
            acc[i][0] = fmaf(xv.x, w0.x, acc[i][0]); acc[i][0] = fmaf(xv.y, w0.y, acc[i][0]);
            acc[i][0] = fmaf(xv.z, w0.z, acc[i][0]); acc[i][0] = fmaf(xv.w, w0.w, acc[i][0]);
            acc[i][1] = fmaf(xv.x, w1.x, acc[i][1]); acc[i][1] = fmaf(xv.y, w1.y, acc[i][1]);
            acc[i][1] = fmaf(xv.z, w1.z, acc[i][1]); acc[i][1] = fmaf(xv.w, w1.w, acc[i][1]);
            acc[i][2] = fmaf(xv.x, w2.x, acc[i][2]); acc[i][2] = fmaf(xv.y, w2.y, acc[i][2]);
            acc[i][2] = fmaf(xv.z, w2.z, acc[i][2]); acc[i][2] = fmaf(xv.w, w2.w, acc[i][2]);
            acc[i][3] = fmaf(xv.x, w3.x, acc[i][3]); acc[i][3] = fmaf(xv.y, w3.y, acc[i][3]);
            acc[i][3] = fmaf(xv.z, w3.z, acc[i][3]); acc[i][3] = fmaf(xv.w, w3.w, acc[i][3]);
        }
    }

    #pragma unroll
    for (int i = 0; i < 4; i++)
        #pragma unroll
        for (int j = 0; j < 4; j++)
            acc[i][j] += __shfl_xor_sync(0xffffffffu, acc[i][j], 1);

    if (kh == 0) {
        #pragma unroll
        for (int i = 0; i < 4; i++) {
            const int r = rt * 4 + i;
            const int b = bt * 8 + (r >> 2);
            const int p = r & 3;
            const float g = s_g[r];
            #pragma unroll
            for (int j = 0; j < 4; j++) {
                const int hl = ht + j * 16;
                g_partial[b][e][p * D + htb * 64 + hl] = g * (acc[i][j] + s_be[hl]);
            }
        }
    }
}

// ---------------------------------------------------------------------------
// K3: combine experts, de-normalize, head matvec.
// grid = (32 b, 24 t-tiles), 128 threads; 4 warps -> 4 outputs per block.
// ---------------------------------------------------------------------------
__global__ void __launch_bounds__(128)
k3_head(const float* __restrict__ W_head,
        const float* __restrict__ b_head,
        float* __restrict__ out) {
    const int b    = blockIdx.x;
    const int tid  = threadIdx.x;
    const int warp = tid >> 5;
    const int lane = tid & 31;

    __shared__ __align__(16) float s_t[LSEQ];

    const float mean = g_stats[b][0];
    const float sd   = g_stats[b][1];

    const float4* gp = reinterpret_cast<const float4*>(&g_partial[b][0][0]);
    #pragma unroll
    for (int c = 0; c < 2; c++) {
        const int i = tid + c * 128;
        float4 acc = make_float4(0.f, 0.f, 0.f, 0.f);
        #pragma unroll
        for (int e = 0; e < NE; e++) {
            const float4 v = gp[e * 256 + i];
            acc.x += v.x; acc.y += v.y; acc.z += v.z; acc.w += v.w;
        }
        reinterpret_cast<float4*>(s_t)[i] =
            make_float4(fmaf(acc.x, sd, mean), fmaf(acc.y, sd, mean),
                        fmaf(acc.z, sd, mean), fmaf(acc.w, sd, mean));
    }
    __syncthreads();

    const int t = blockIdx.y * 4 + warp;
    const float4* wr = reinterpret_cast<const float4*>(W_head + (size_t)t * LSEQ);
    const float4* tt = reinterpret_cast<const float4*>(s_t);
    float ax = 0.f, ay = 0.f, az = 0.f, aw = 0.f;
    #pragma unroll
    for (int q = 0; q < 8; q++) {
        const int i = q * 32 + lane;
        const float4 w = wr[i];
        const float4 f = tt[i];
        ax = fmaf(w.x, f.x, ax);
        ay = fmaf(w.y, f.y, ay);
        az = fmaf(w.z, f.z, az);
        aw = fmaf(w.w, f.w, aw);
    }
    float r = (ax + ay) + (az + aw);
    #pragma unroll
    for (int o = 16; o; o >>= 1) r += __shfl_xor_sync(0xffffffffu, r, o);
    if (lane == 0) out[b * PRED + t] = r + b_head[t];
}

// ---------------------------------------------------------------------------
extern "C" void kernel_launch(void* const* d_in, const int* in_sizes, int n_in,
                              void* d_out, int out_size) {
    const float* x         = (const float*)d_in[0];
    const float* W_proj    = (const float*)d_in[4];
    const float* b_proj    = (const float*)d_in[5];
    const float* W_router  = (const float*)d_in[6];
    const float* b_router  = (const float*)d_in[7];
    const float* W_experts = (const float*)d_in[8];
    const float* b_experts = (const float*)d_in[9];
    const float* W_head    = (const float*)d_in[10];
    const float* b_head    = (const float*)d_in[11];
    float* out = (float*)d_out;

    cudaFuncSetAttribute(k2_experts,
                         cudaFuncAttributeMaxDynamicSharedMemorySize,
                         K2_SMEM_BYTES);

    k0_stats<<<NB * 8, 128>>>(x, W_experts, W_head);
    k1_prep<<<NB, 256>>>(x, W_proj, b_proj, W_router, b_router);
    dim3 g2(NE, NB / 8, NP);
    k2_experts<<<g2, 256, K2_SMEM_BYTES>>>(W_experts, b_experts);
    dim3 g3(NB, PRED / 4);
    k3_head<<<g3, 128>>>(W_head, b_head, out);
}